// round 15
// baseline (speedup 1.0000x reference)
#include <cuda_runtime.h>
#include <cuda_bf16.h>

// Problem constants
#define NN    3072
#define EE    98304
#define OUTD  5
#define ROWF  27648          // N*9 floats per R row
#define BT    288            // threads per block (288*4 = 1152, divisible by 9)
#define ITERS 24             // 6912 float4s / 288
#define TAILB 96             // tail worker blocks (must all fit in wave 1)
#define TAILT (TAILB*BT)     // 27648 tail threads
#define TAILW (TAILB*9)      // 864 tail warps
#define RBLK  (NN/2)         // R writer blocks, 2 rows each

// ---------------- scratch ----------------
__device__ __align__(16) float g_Ab[NN * 9];
__device__ __align__(16) float g_Bf[NN * 9];
__device__ int   g_deg[NN];
__device__ int   g_cur[NN];
__device__ int   g_off[NN + 1];
__device__ int   g_csr[EE];
__device__ __align__(16) float g_out36[NN * 36];
__device__ int   g_bar_cnt;
__device__ int   g_bar_phase;

// ---------------- fast tanh: 2 MUFU + 3 FMA ----------------
__device__ __forceinline__ float tanh_fast(float x) {
    float t = x * 2.885390081777927f;
    float e;
    asm("ex2.approx.ftz.f32 %0, %1;" : "=f"(e) : "f"(t));
    float r;
    asm("rcp.approx.ftz.f32 %0, %1;" : "=f"(r) : "f"(e + 1.0f));
    return fmaf(-2.0f, r, 1.0f);
}

// ---------------- global spin barrier among TAILB blocks ----------------
__device__ __forceinline__ void tail_barrier() {
    __syncthreads();
    if (threadIdx.x == 0) {
        __threadfence();
        int ph = atomicAdd(&g_bar_phase, 0);
        int old = atomicAdd(&g_bar_cnt, 1);
        if (old == TAILB - 1) {
            g_bar_cnt = 0;
            __threadfence();
            atomicAdd(&g_bar_phase, 1);
        } else {
            while (atomicAdd(&g_bar_phase, 0) == ph) { }
        }
        __threadfence();
    }
    __syncthreads();
}

// ---------------- K0: per-node sheaf factors + zero counters ----------------
__global__ void k_prep(const float* __restrict__ x,
                       const float* __restrict__ Ws,
                       const float* __restrict__ bs) {
    int n = blockIdx.x * blockDim.x + threadIdx.x;
    if (n >= NN) return;
    if (n == 0) g_bar_cnt = 0;
    g_deg[n] = 0; g_cur[n] = 0;
    float x0 = x[n*3+0], x1 = x[n*3+1], x2 = x[n*3+2];
#pragma unroll
    for (int c = 0; c < 9; c++) {
        g_Ab[n*9+c] = fmaf(x0, Ws[c], fmaf(x1, Ws[9+c], fmaf(x2, Ws[18+c], bs[c])));
        g_Bf[n*9+c] = fmaf(x0, Ws[27+c], fmaf(x1, Ws[36+c], x2 * Ws[45+c]));
    }
}

// ---------- fused: tail pipeline (blocks 0..95) + R rows (2 rows/block after) ----------
__global__ __launch_bounds__(BT, 4) void k_fused(
        const float* __restrict__ x,
        const int*   __restrict__ ei,
        const float* __restrict__ Kv,
        const float* __restrict__ Wc, const float* __restrict__ bc,
        const float* __restrict__ W1, const float* __restrict__ b1,
        const float* __restrict__ W2, const float* __restrict__ b2,
        float* __restrict__ out, float* __restrict__ R) {
    int tid = threadIdx.x;

    if (blockIdx.x >= TAILB) {
        // ---------------- R writer block: rows i0 and i0+1 ----------------
        int i0 = (blockIdx.x - TAILB) * 2;
        __shared__ float sA[18];
        if (tid < 18) sA[tid] = g_Ab[i0 * 9 + tid];
        __syncthreads();
        int c0 = (4 * tid) % 9;             // 1152 % 9 == 0 -> loop-invariant residues
        int c1 = (c0 + 1) % 9, c2 = (c0 + 2) % 9, c3 = (c0 + 3) % 9;
        float a0 = sA[c0],     a1 = sA[c1],     a2 = sA[c2],     a3 = sA[c3];
        float d0 = sA[9 + c0], d1 = sA[9 + c1], d2 = sA[9 + c2], d3 = sA[9 + c3];
        const float4* __restrict__ B = (const float4*)g_Bf;
        float4* __restrict__ dst0 = (float4*)(R + (size_t)i0 * ROWF);
        float4* __restrict__ dst1 = (float4*)(R + (size_t)(i0 + 1) * ROWF);
#pragma unroll 6
        for (int it = 0; it < ITERS; it++) {
            int idx = tid + it * BT;
            float4 b = B[idx];
            float4 o0, o1;
            o0.x = tanh_fast(a0 + b.x); o1.x = tanh_fast(d0 + b.x);
            o0.y = tanh_fast(a1 + b.y); o1.y = tanh_fast(d1 + b.y);
            o0.z = tanh_fast(a2 + b.z); o1.z = tanh_fast(d2 + b.z);
            o0.w = tanh_fast(a3 + b.w); o1.w = tanh_fast(d3 + b.w);
            __stcs(&dst0[idx], o0);
            __stcs(&dst1[idx], o1);
        }
        return;
    }

    // ---------------- tail worker block ----------------
    int bid  = blockIdx.x;
    int gtid = bid * BT + tid;           // 0..27647
    int lane = tid & 31;
    int wid  = tid >> 5;                 // 0..8
    int gw   = bid * 9 + wid;            // 0..863

    __shared__ int   wsum[10];
    __shared__ float sconv[9][36];
    __shared__ float shid[9][64];

    // --- Stage A: in-degree count ---
    for (int e = gtid; e < EE; e += TAILT)
        atomicAdd(&g_deg[ei[EE + e]], 1);
    tail_barrier();

    // --- Stage B: exclusive scan (block 0 only) ---
    if (bid == 0) {
        const int D = 11;                // 288*11 = 3168 >= 3072
        int base = tid * D;
        int vals[D];
        int sum = 0;
#pragma unroll
        for (int k = 0; k < D; k++) {
            int idx = base + k;
            int v = (idx < NN) ? g_deg[idx] : 0;
            vals[k] = sum; sum += v;
        }
        int incl = sum;
#pragma unroll
        for (int off = 1; off < 32; off <<= 1) {
            int v = __shfl_up_sync(0xffffffffu, incl, off);
            if (lane >= off) incl += v;
        }
        if (lane == 31) wsum[wid] = incl;
        __syncthreads();
        if (tid == 0) {
            int run = 0;
#pragma unroll
            for (int i2 = 0; i2 < 9; i2++) { int v = wsum[i2]; wsum[i2] = run; run += v; }
            g_off[NN] = run;
        }
        __syncthreads();
        int tOff = wsum[wid] + (incl - sum);
#pragma unroll
        for (int k = 0; k < D; k++) {
            int idx = base + k;
            if (idx < NN) g_off[idx] = tOff + vals[k];
        }
    }
    tail_barrier();

    // --- Stage C: CSR fill ---
    for (int e = gtid; e < EE; e += TAILT) {
        int t = ei[EE + e];
        int p = g_off[t] + atomicAdd(&g_cur[t], 1);
        g_csr[p] = e;
    }
    tail_barrier();

    // --- Stage D: hop 1 (warp per node) ---
    for (int n = gw; n < NN; n += TAILW) {
        float acc[9];
#pragma unroll
        for (int c = 0; c < 9; c++) acc[c] = 0.f;
        int beg = g_off[n], end = g_off[n + 1];
        for (int p = beg + lane; p < end; p += 32) {
            int e = g_csr[p];
            int s = ei[e];
            float xs0 = __ldg(&x[s*3+0]), xs1 = __ldg(&x[s*3+1]), xs2 = __ldg(&x[s*3+2]);
            float k0 = Kv[e], k1 = Kv[EE + e], k2 = Kv[2*EE + e];
            acc[0] = fmaf(k0, xs0, acc[0]); acc[1] = fmaf(k0, xs1, acc[1]); acc[2] = fmaf(k0, xs2, acc[2]);
            acc[3] = fmaf(k1, xs0, acc[3]); acc[4] = fmaf(k1, xs1, acc[4]); acc[5] = fmaf(k1, xs2, acc[5]);
            acc[6] = fmaf(k2, xs0, acc[6]); acc[7] = fmaf(k2, xs1, acc[7]); acc[8] = fmaf(k2, xs2, acc[8]);
        }
#pragma unroll
        for (int off = 16; off; off >>= 1)
#pragma unroll
            for (int c = 0; c < 9; c++) acc[c] += __shfl_xor_sync(0xffffffffu, acc[c], off);
        if (lane == 0) {
            float* dst = g_out36 + (size_t)n * 36;
            *(float4*)(dst)     = make_float4(acc[0], acc[1], acc[2], acc[3]);
            *(float4*)(dst + 4) = make_float4(acc[4], acc[5], acc[6], acc[7]);
            dst[8] = acc[8];
        }
    }
    tail_barrier();

    // --- Stage E: hop 2 ---
    for (int n = gw; n < NN; n += TAILW) {
        float acc[27];
#pragma unroll
        for (int c = 0; c < 27; c++) acc[c] = 0.f;
        int beg = g_off[n], end = g_off[n + 1];
        for (int p = beg + lane; p < end; p += 32) {
            int e = g_csr[p];
            int s = ei[e];
            const float* hr = g_out36 + (size_t)s * 36;
            float4 h0 = *(const float4*)(hr);
            float4 h1v = *(const float4*)(hr + 4);
            float h8 = hr[8];
            float hv[9] = {h0.x, h0.y, h0.z, h0.w, h1v.x, h1v.y, h1v.z, h1v.w, h8};
            float k0 = Kv[e], k1 = Kv[EE + e], k2 = Kv[2*EE + e];
#pragma unroll
            for (int c = 0; c < 9; c++) {
                acc[c]      = fmaf(k0, hv[c], acc[c]);
                acc[9 + c]  = fmaf(k1, hv[c], acc[9 + c]);
                acc[18 + c] = fmaf(k2, hv[c], acc[18 + c]);
            }
        }
#pragma unroll
        for (int off = 16; off; off >>= 1)
#pragma unroll
            for (int c = 0; c < 27; c++) acc[c] += __shfl_xor_sync(0xffffffffu, acc[c], off);
        if (lane == 0) {
            float* dst = g_out36 + (size_t)n * 36 + 9;
#pragma unroll
            for (int c = 0; c < 27; c++) dst[c] = acc[c];
        }
    }
    tail_barrier();

    // --- Stage F: GCN mean-agg + W_conv + MLP head ---
    for (int n = gw; n < NN; n += TAILW) {
        float acc[36];
#pragma unroll
        for (int c = 0; c < 36; c++) acc[c] = 0.f;
        int beg = g_off[n], end = g_off[n + 1];
        for (int p = beg + lane; p < end; p += 32) {
            int e = g_csr[p];
            int s = ei[e];
            const float4* r = (const float4*)(g_out36 + (size_t)s * 36);
#pragma unroll
            for (int q = 0; q < 9; q++) {
                float4 v = r[q];
                acc[4*q+0] += v.x; acc[4*q+1] += v.y; acc[4*q+2] += v.z; acc[4*q+3] += v.w;
            }
        }
#pragma unroll
        for (int off = 16; off; off >>= 1)
#pragma unroll
            for (int c = 0; c < 36; c++) acc[c] += __shfl_xor_sync(0xffffffffu, acc[c], off);
        float invd = 1.0f / fmaxf((float)(end - beg), 1.0f);
#pragma unroll
        for (int c = 0; c < 36; c++) acc[c] *= invd;
#pragma unroll
        for (int jb = 0; jb < 2; jb++) {
            int j = lane + 32 * jb;
            if (j < 36) {
                float s = bc[j];
#pragma unroll
                for (int c = 0; c < 36; c++) s = fmaf(acc[c], Wc[c*36 + j], s);
                sconv[wid][j] = fmaxf(s, 0.f);
            }
        }
        __syncwarp();
#pragma unroll
        for (int hb = 0; hb < 2; hb++) {
            int h = lane + 32 * hb;
            float s = b1[h];
#pragma unroll
            for (int j = 0; j < 36; j++) s = fmaf(sconv[wid][j], W1[j*64 + h], s);
            shid[wid][h] = fmaxf(s, 0.f);
        }
        __syncwarp();
        if (lane < OUTD) {
            float s = b2[lane];
#pragma unroll
            for (int h = 0; h < 64; h++) s = fmaf(shid[wid][h], W2[h*5 + lane], s);
            out[(size_t)n * 5 + lane] = s;
        }
        __syncwarp();
    }
}

// ---------------- launch ----------------
extern "C" void kernel_launch(void* const* d_in, const int* in_sizes, int n_in,
                              void* d_out, int out_size) {
    const float* x  = (const float*)d_in[0];
    const int*   ei = (const int*)d_in[1];      // int32 [2, E]
    const float* Kv = (const float*)d_in[2];
    const float* Ws = (const float*)d_in[3];
    const float* bs = (const float*)d_in[4];
    const float* Wc = (const float*)d_in[5];
    const float* bc = (const float*)d_in[6];
    const float* W1 = (const float*)d_in[7];
    const float* b1 = (const float*)d_in[8];
    const float* W2 = (const float*)d_in[9];
    const float* b2 = (const float*)d_in[10];
    float* out  = (float*)d_out;
    float* Rout = out + (size_t)NN * OUTD;

    k_prep<<<(NN + 255) / 256, 256>>>(x, Ws, bs);
    k_fused<<<TAILB + RBLK, BT>>>(x, ei, Kv, Wc, bc, W1, b1, W2, b2, out, Rout);
}

// round 16
// speedup vs baseline: 1.1525x; 1.1525x over previous
#include <cuda_runtime.h>
#include <cuda_bf16.h>

// Problem constants
#define NN    3072
#define EE    98304
#define OUTD  5
#define ROWF  27648          // N*9 floats per R row
#define BT    288            // threads per block (288*4 = 1152, divisible by 9)
#define ITERS 24             // 6912 float4s / 288
#define TAILB 96             // tail worker blocks (must all fit in wave 1)
#define TAILT (TAILB*BT)     // 27648 tail threads
#define TAILW (TAILB*9)      // 864 tail warps

// ---------------- scratch ----------------
__device__ __align__(16) float g_Ab[NN * 9];
__device__ __align__(16) float g_Bf[NN * 9];
__device__ int   g_deg[NN];
__device__ int   g_cur[NN];
__device__ int   g_off[NN + 1];
__device__ int   g_csr[EE];
__device__ __align__(16) float g_out36[NN * 36];
__device__ int   g_bar_cnt;
__device__ int   g_bar_phase;

// ---------------- hardware tanh: single MUFU op (sm_75+) ----------------
__device__ __forceinline__ float tanh_hw(float x) {
    float r;
    asm("tanh.approx.f32 %0, %1;" : "=f"(r) : "f"(x));
    return r;
}

// ---------------- global spin barrier among TAILB blocks ----------------
__device__ __forceinline__ void tail_barrier() {
    __syncthreads();
    if (threadIdx.x == 0) {
        __threadfence();
        int ph = atomicAdd(&g_bar_phase, 0);
        int old = atomicAdd(&g_bar_cnt, 1);
        if (old == TAILB - 1) {
            g_bar_cnt = 0;
            __threadfence();
            atomicAdd(&g_bar_phase, 1);
        } else {
            while (atomicAdd(&g_bar_phase, 0) == ph) { }
        }
        __threadfence();
    }
    __syncthreads();
}

// ---------------- K0: per-node sheaf factors + zero counters ----------------
__global__ void k_prep(const float* __restrict__ x,
                       const float* __restrict__ Ws,
                       const float* __restrict__ bs) {
    int n = blockIdx.x * blockDim.x + threadIdx.x;
    if (n >= NN) return;
    if (n == 0) g_bar_cnt = 0;
    g_deg[n] = 0; g_cur[n] = 0;
    float x0 = x[n*3+0], x1 = x[n*3+1], x2 = x[n*3+2];
#pragma unroll
    for (int c = 0; c < 9; c++) {
        g_Ab[n*9+c] = fmaf(x0, Ws[c], fmaf(x1, Ws[9+c], fmaf(x2, Ws[18+c], bs[c])));
        g_Bf[n*9+c] = fmaf(x0, Ws[27+c], fmaf(x1, Ws[36+c], x2 * Ws[45+c]));
    }
}

// ---------- fused: tail pipeline (blocks 0..95) + R rows (1 row/block after) ----------
__global__ __launch_bounds__(BT) void k_fused(
        const float* __restrict__ x,
        const int*   __restrict__ ei,
        const float* __restrict__ Kv,
        const float* __restrict__ Wc, const float* __restrict__ bc,
        const float* __restrict__ W1, const float* __restrict__ b1,
        const float* __restrict__ W2, const float* __restrict__ b2,
        float* __restrict__ out, float* __restrict__ R) {
    int tid = threadIdx.x;

    if (blockIdx.x >= TAILB) {
        // ---------------- R writer block ----------------
        int i = blockIdx.x - TAILB;
        __shared__ float sA[9];
        if (tid < 9) sA[tid] = g_Ab[i * 9 + tid];
        __syncthreads();
        int c0 = (4 * tid) % 9;             // 1152 % 9 == 0 -> loop-invariant residues
        float av0 = sA[c0];
        float av1 = sA[(c0 + 1) % 9];
        float av2 = sA[(c0 + 2) % 9];
        float av3 = sA[(c0 + 3) % 9];
        const float4* __restrict__ B = (const float4*)g_Bf;
        float4* __restrict__ dst = (float4*)(R + (size_t)i * ROWF);
#pragma unroll 8
        for (int it = 0; it < ITERS; it++) {
            int idx = tid + it * BT;
            float4 b = B[idx];
            float4 o;
            o.x = tanh_hw(av0 + b.x);
            o.y = tanh_hw(av1 + b.y);
            o.z = tanh_hw(av2 + b.z);
            o.w = tanh_hw(av3 + b.w);
            __stcs(&dst[idx], o);
        }
        return;
    }

    // ---------------- tail worker block ----------------
    int bid  = blockIdx.x;
    int gtid = bid * BT + tid;           // 0..27647
    int lane = tid & 31;
    int wid  = tid >> 5;                 // 0..8
    int gw   = bid * 9 + wid;            // 0..863

    __shared__ int   wsum[10];
    __shared__ float sconv[9][36];
    __shared__ float shid[9][64];

    // --- Stage A: in-degree count ---
    for (int e = gtid; e < EE; e += TAILT)
        atomicAdd(&g_deg[ei[EE + e]], 1);
    tail_barrier();

    // --- Stage B: exclusive scan (block 0 only) ---
    if (bid == 0) {
        const int D = 11;                // 288*11 = 3168 >= 3072
        int base = tid * D;
        int vals[D];
        int sum = 0;
#pragma unroll
        for (int k = 0; k < D; k++) {
            int idx = base + k;
            int v = (idx < NN) ? g_deg[idx] : 0;
            vals[k] = sum; sum += v;
        }
        int incl = sum;
#pragma unroll
        for (int off = 1; off < 32; off <<= 1) {
            int v = __shfl_up_sync(0xffffffffu, incl, off);
            if (lane >= off) incl += v;
        }
        if (lane == 31) wsum[wid] = incl;
        __syncthreads();
        if (tid == 0) {
            int run = 0;
#pragma unroll
            for (int i2 = 0; i2 < 9; i2++) { int v = wsum[i2]; wsum[i2] = run; run += v; }
            g_off[NN] = run;
        }
        __syncthreads();
        int tOff = wsum[wid] + (incl - sum);
#pragma unroll
        for (int k = 0; k < D; k++) {
            int idx = base + k;
            if (idx < NN) g_off[idx] = tOff + vals[k];
        }
    }
    tail_barrier();

    // --- Stage C: CSR fill ---
    for (int e = gtid; e < EE; e += TAILT) {
        int t = ei[EE + e];
        int p = g_off[t] + atomicAdd(&g_cur[t], 1);
        g_csr[p] = e;
    }
    tail_barrier();

    // --- Stage D: hop 1 (warp per node) ---
    for (int n = gw; n < NN; n += TAILW) {
        float acc[9];
#pragma unroll
        for (int c = 0; c < 9; c++) acc[c] = 0.f;
        int beg = g_off[n], end = g_off[n + 1];
        for (int p = beg + lane; p < end; p += 32) {
            int e = g_csr[p];
            int s = ei[e];
            float xs0 = __ldg(&x[s*3+0]), xs1 = __ldg(&x[s*3+1]), xs2 = __ldg(&x[s*3+2]);
            float k0 = Kv[e], k1 = Kv[EE + e], k2 = Kv[2*EE + e];
            acc[0] = fmaf(k0, xs0, acc[0]); acc[1] = fmaf(k0, xs1, acc[1]); acc[2] = fmaf(k0, xs2, acc[2]);
            acc[3] = fmaf(k1, xs0, acc[3]); acc[4] = fmaf(k1, xs1, acc[4]); acc[5] = fmaf(k1, xs2, acc[5]);
            acc[6] = fmaf(k2, xs0, acc[6]); acc[7] = fmaf(k2, xs1, acc[7]); acc[8] = fmaf(k2, xs2, acc[8]);
        }
#pragma unroll
        for (int off = 16; off; off >>= 1)
#pragma unroll
            for (int c = 0; c < 9; c++) acc[c] += __shfl_xor_sync(0xffffffffu, acc[c], off);
        if (lane == 0) {
            float* dst = g_out36 + (size_t)n * 36;
            *(float4*)(dst)     = make_float4(acc[0], acc[1], acc[2], acc[3]);
            *(float4*)(dst + 4) = make_float4(acc[4], acc[5], acc[6], acc[7]);
            dst[8] = acc[8];
        }
    }
    tail_barrier();

    // --- Stage E: hop 2 ---
    for (int n = gw; n < NN; n += TAILW) {
        float acc[27];
#pragma unroll
        for (int c = 0; c < 27; c++) acc[c] = 0.f;
        int beg = g_off[n], end = g_off[n + 1];
        for (int p = beg + lane; p < end; p += 32) {
            int e = g_csr[p];
            int s = ei[e];
            const float* hr = g_out36 + (size_t)s * 36;
            float4 h0 = *(const float4*)(hr);
            float4 h1v = *(const float4*)(hr + 4);
            float h8 = hr[8];
            float hv[9] = {h0.x, h0.y, h0.z, h0.w, h1v.x, h1v.y, h1v.z, h1v.w, h8};
            float k0 = Kv[e], k1 = Kv[EE + e], k2 = Kv[2*EE + e];
#pragma unroll
            for (int c = 0; c < 9; c++) {
                acc[c]      = fmaf(k0, hv[c], acc[c]);
                acc[9 + c]  = fmaf(k1, hv[c], acc[9 + c]);
                acc[18 + c] = fmaf(k2, hv[c], acc[18 + c]);
            }
        }
#pragma unroll
        for (int off = 16; off; off >>= 1)
#pragma unroll
            for (int c = 0; c < 27; c++) acc[c] += __shfl_xor_sync(0xffffffffu, acc[c], off);
        if (lane == 0) {
            float* dst = g_out36 + (size_t)n * 36 + 9;
#pragma unroll
            for (int c = 0; c < 27; c++) dst[c] = acc[c];
        }
    }
    tail_barrier();

    // --- Stage F: GCN mean-agg + W_conv + MLP head ---
    for (int n = gw; n < NN; n += TAILW) {
        float acc[36];
#pragma unroll
        for (int c = 0; c < 36; c++) acc[c] = 0.f;
        int beg = g_off[n], end = g_off[n + 1];
        for (int p = beg + lane; p < end; p += 32) {
            int e = g_csr[p];
            int s = ei[e];
            const float4* r = (const float4*)(g_out36 + (size_t)s * 36);
#pragma unroll
            for (int q = 0; q < 9; q++) {
                float4 v = r[q];
                acc[4*q+0] += v.x; acc[4*q+1] += v.y; acc[4*q+2] += v.z; acc[4*q+3] += v.w;
            }
        }
#pragma unroll
        for (int off = 16; off; off >>= 1)
#pragma unroll
            for (int c = 0; c < 36; c++) acc[c] += __shfl_xor_sync(0xffffffffu, acc[c], off);
        float invd = 1.0f / fmaxf((float)(end - beg), 1.0f);
#pragma unroll
        for (int c = 0; c < 36; c++) acc[c] *= invd;
#pragma unroll
        for (int jb = 0; jb < 2; jb++) {
            int j = lane + 32 * jb;
            if (j < 36) {
                float s = bc[j];
#pragma unroll
                for (int c = 0; c < 36; c++) s = fmaf(acc[c], Wc[c*36 + j], s);
                sconv[wid][j] = fmaxf(s, 0.f);
            }
        }
        __syncwarp();
#pragma unroll
        for (int hb = 0; hb < 2; hb++) {
            int h = lane + 32 * hb;
            float s = b1[h];
#pragma unroll
            for (int j = 0; j < 36; j++) s = fmaf(sconv[wid][j], W1[j*64 + h], s);
            shid[wid][h] = fmaxf(s, 0.f);
        }
        __syncwarp();
        if (lane < OUTD) {
            float s = b2[lane];
#pragma unroll
            for (int h = 0; h < 64; h++) s = fmaf(shid[wid][h], W2[h*5 + lane], s);
            out[(size_t)n * 5 + lane] = s;
        }
        __syncwarp();
    }
}

// ---------------- launch ----------------
extern "C" void kernel_launch(void* const* d_in, const int* in_sizes, int n_in,
                              void* d_out, int out_size) {
    const float* x  = (const float*)d_in[0];
    const int*   ei = (const int*)d_in[1];      // int32 [2, E]
    const float* Kv = (const float*)d_in[2];
    const float* Ws = (const float*)d_in[3];
    const float* bs = (const float*)d_in[4];
    const float* Wc = (const float*)d_in[5];
    const float* bc = (const float*)d_in[6];
    const float* W1 = (const float*)d_in[7];
    const float* b1 = (const float*)d_in[8];
    const float* W2 = (const float*)d_in[9];
    const float* b2 = (const float*)d_in[10];
    float* out  = (float*)d_out;
    float* Rout = out + (size_t)NN * OUTD;

    k_prep<<<(NN + 255) / 256, 256>>>(x, Ws, bs);
    k_fused<<<TAILB + NN, BT>>>(x, ei, Kv, Wc, bc, W1, b1, W2, b2, out, Rout);
}